// round 11
// baseline (speedup 1.0000x reference)
#include <cuda_runtime.h>
#include <math.h>
#include <stdint.h>

// ---------------------------------------------------------------------------
// PhaseQuantizer: 2-step residual phase quantization, minimal-traffic plan.
//   pass1: masked abs-sum stats of w               (reads 8n bytes)
//   pass2: [inline reduce s1] eval q1, stats(err1)  (reads 8n)
//   pass3: [inline reduce s1,s2] q1,q2 -> out       (reads 8n, writes 8n)
// Eval: psi>=0 + E=e^2 factorization, 3 MUFU per element; ALL FMA-pipe work
// (poly, exp algebra, softmax, residual subtraction, scaling, q1+q2) runs as
// packed f32x2 with u64 I/O end-to-end. Scalar only: min/max/setp/copysign
// select glue and MUFU.
// pass1 single-wave 4x unroll; pass2/3 depth-2 register pipeline, 2 waves.
// ---------------------------------------------------------------------------

namespace {
constexpr int   NBLK_MAX = 2560;
constexpr int   NTHR  = 256;
constexpr float PI_F  = 3.14159265358979323846f;
constexpr float LOG2E = 1.44269504088896340736f;
}

typedef unsigned long long u64;

struct Part { float sre, sim; int cre, cim; };
__device__ Part g_part1[NBLK_MAX];
__device__ Part g_part2[NBLK_MAX];

__device__ __forceinline__ float ex2f(float x) {
    float y; asm("ex2.approx.f32 %0, %1;" : "=f"(y) : "f"(x)); return y;
}
__device__ __forceinline__ float rcpf(float x) {
    float y; asm("rcp.approx.f32 %0, %1;" : "=f"(y) : "f"(x)); return y;
}

// ---- packed f32x2 helpers (sm_103a) ----
__device__ __forceinline__ u64 pk(float lo, float hi) {
    u64 r; asm("mov.b64 %0, {%1, %2};" : "=l"(r) : "f"(lo), "f"(hi)); return r;
}
__device__ __forceinline__ void upk(u64 v, float& lo, float& hi) {
    asm("mov.b64 {%0, %1}, %2;" : "=f"(lo), "=f"(hi) : "l"(v));
}
__device__ __forceinline__ u64 fma2(u64 a, u64 b, u64 c) {
    u64 d; asm("fma.rn.f32x2 %0, %1, %2, %3;" : "=l"(d) : "l"(a), "l"(b), "l"(c));
    return d;
}
__device__ __forceinline__ u64 mul2(u64 a, u64 b) {
    u64 d; asm("mul.rn.f32x2 %0, %1, %2;" : "=l"(d) : "l"(a), "l"(b));
    return d;
}
__device__ __forceinline__ u64 add2(u64 a, u64 b) {
    u64 d; asm("add.rn.f32x2 %0, %1, %2;" : "=l"(d) : "l"(a), "l"(b));
    return d;
}

struct Coef {
    float p0, p1, p2, p3, p4;  // atan poly coeffs prescaled by (pi/t)*log2(e)
    float c1, c3;              // exp(-pi^2/(4t)), exp(-pi^2/t)
};

struct PCoef {                 // packed (duplicated-half) constants
    u64 p0, p1, p2, p3, p4;
    u64 c1, negc1, c3, one, negone;
    u64 sre, sim;              // packed step scales
};

__device__ __forceinline__ Coef make_coef(const float* temp) {
    float t = __ldg(temp) + 1e-6f;
    float inv_t = 1.0f / t;
    float kl = PI_F * inv_t * LOG2E;
    Coef c;
    // Abramowitz & Stegun 4.4.49 atan poly (|x|<=1, |err|<=1e-5 rad)
    c.p0 =  0.9998660f * kl;
    c.p1 = -0.3302995f * kl;
    c.p2 =  0.1801410f * kl;
    c.p3 = -0.0851330f * kl;
    c.p4 =  0.0208351f * kl;
    c.c1 = __expf(-(PI_F * PI_F * 0.25f) * inv_t);
    c.c3 = c.c1 * c.c1; c.c3 = c.c3 * c.c3;
    return c;
}

__device__ __forceinline__ PCoef make_pcoef(const Coef& c, float2 s) {
    PCoef p;
    p.p0 = pk(c.p0, c.p0); p.p1 = pk(c.p1, c.p1); p.p2 = pk(c.p2, c.p2);
    p.p3 = pk(c.p3, c.p3); p.p4 = pk(c.p4, c.p4);
    p.c1 = pk(c.c1, c.c1); p.negc1 = pk(-c.c1, -c.c1);
    p.c3 = pk(c.c3, c.c3);
    p.one = pk(1.0f, 1.0f); p.negone = pk(-1.0f, -1.0f);
    p.sre = pk(s.x, s.x); p.sim = pk(s.y, s.y);
    return p;
}

// Scalar eval (tail paths only).
__device__ __forceinline__ void quant_eval(float re, float im,
                                           float sre, float sim,
                                           const Coef& c,
                                           float& qre, float& qim) {
    float ar = fabsf(re), ai = fabsf(im);
    bool  rd = (ar >= ai);
    float m  = fmaxf(fmaxf(ar, ai), 1e-30f);
    float nm = fminf(ar, ai);
    float r  = nm * rcpf(m);
    float r2 = r * r;
    float p  = fmaf(r2, c.p4, c.p3);
    p = fmaf(r2, p, c.p2);
    p = fmaf(r2, p, c.p1);
    p = fmaf(r2, p, c.p0);
    float v  = r * p;
    float e  = ex2f(v);
    float E  = e * e;
    float uo = c.c3 * E;
    float t2 = fmaf(e, uo, e);
    float eD = fmaf(c.c1, E + 1.0f, t2);
    float rD = rcpf(eD);
    float P  = fmaf(2.0f, e, -t2) * rD;
    float Qa = fmaf(c.c1, E, -c.c1) * rD;
    float pr = rd ? P  : Qa;
    float pi = rd ? Qa : P;
    qre = copysignf(pr, re) * sre;
    qim = copysignf(pi, im) * sim;
}

// Packed pair eval with u64 I/O: two independent elements share all FMA-pipe
// chains as f32x2. Identical IEEE-rn arithmetic to the scalar version.
__device__ __forceinline__ void quant_eval2p(u64 re01, u64 im01,
                                             const PCoef& pc,
                                             u64& qre01, u64& qim01) {
    float re0, re1, im0, im1;
    upk(re01, re0, re1); upk(im01, im0, im1);
    float ar0 = fabsf(re0), ai0 = fabsf(im0);
    float ar1 = fabsf(re1), ai1 = fabsf(im1);
    bool  rd0 = (ar0 >= ai0), rd1 = (ar1 >= ai1);
    float m0  = fmaxf(fmaxf(ar0, ai0), 1e-30f);
    float m1  = fmaxf(fmaxf(ar1, ai1), 1e-30f);
    float nm0 = fminf(ar0, ai0), nm1 = fminf(ar1, ai1);
    u64 r  = mul2(pk(nm0, nm1), pk(rcpf(m0), rcpf(m1)));
    u64 r2 = mul2(r, r);
    u64 p  = fma2(r2, pc.p4, pc.p3);
    p = fma2(r2, p, pc.p2);
    p = fma2(r2, p, pc.p1);
    p = fma2(r2, p, pc.p0);
    u64 v = mul2(r, p);
    float v0, v1; upk(v, v0, v1);
    u64 e  = pk(ex2f(v0), ex2f(v1));
    u64 E  = mul2(e, e);
    u64 uo = mul2(pc.c3, E);
    u64 t2 = fma2(e, uo, e);                     // e*(1+uo)
    u64 eD = fma2(pc.c1, add2(E, pc.one), t2);   // e * denominator
    float d0, d1; upk(eD, d0, d1);
    u64 rD = pk(rcpf(d0), rcpf(d1));
    u64 Pn = mul2(fma2(pc.negone, t2, add2(e, e)), rD);  // (2e - t2)/eD
    u64 Qn = mul2(fma2(pc.c1, E, pc.negc1), rD);         // c1(E-1)/eD
    float P0, P1, Q0, Q1;
    upk(Pn, P0, P1); upk(Qn, Q0, Q1);
    float pr0 = copysignf(rd0 ? P0 : Q0, re0);
    float pi0 = copysignf(rd0 ? Q0 : P0, im0);
    float pr1 = copysignf(rd1 ? P1 : Q1, re1);
    float pi1 = copysignf(rd1 ? Q1 : P1, im1);
    qre01 = mul2(pk(pr0, pr1), pc.sre);
    qim01 = mul2(pk(pi0, pi1), pc.sim);
}

__device__ __forceinline__ void acc_stats(float re, float im,
                                          float& sre, float& sim,
                                          int& cre, int& cim) {
    float ar = fabsf(re), ai = fabsf(im);
    if (ar >= ai) { sre += ar; cre++; }
    else          { sim += ai; cim++; }
}

// Deterministic fixed-order block reduce -> per-block partial slot.
__device__ __forceinline__ void stats_reduce_store(Part* part,
                                                   float sre, float sim,
                                                   int cre, int cim) {
    #pragma unroll
    for (int o = 16; o > 0; o >>= 1) {
        sre += __shfl_down_sync(0xffffffffu, sre, o);
        sim += __shfl_down_sync(0xffffffffu, sim, o);
        cre += __shfl_down_sync(0xffffffffu, cre, o);
        cim += __shfl_down_sync(0xffffffffu, cim, o);
    }
    __shared__ float sh_sre[NTHR / 32], sh_sim[NTHR / 32];
    __shared__ int   sh_cre[NTHR / 32], sh_cim[NTHR / 32];
    int lane = threadIdx.x & 31, wrp = threadIdx.x >> 5;
    if (lane == 0) { sh_sre[wrp] = sre; sh_sim[wrp] = sim;
                     sh_cre[wrp] = cre; sh_cim[wrp] = cim; }
    __syncthreads();
    if (threadIdx.x == 0) {
        float a = 0.f, b = 0.f; int cc = 0, d = 0;
        #pragma unroll
        for (int i = 0; i < NTHR / 32; i++) {
            a += sh_sre[i]; b += sh_sim[i]; cc += sh_cre[i]; d += sh_cim[i];
        }
        part[blockIdx.x].sre = a; part[blockIdx.x].sim = b;
        part[blockIdx.x].cre = cc; part[blockIdx.x].cim = d;
    }
}

// Inline final reduce over npart partials; identical fixed-order result in
// every block (deterministic). Returns (s_re, s_im).
__device__ __forceinline__ float2 final_reduce(const Part* __restrict__ part,
                                               int npart,
                                               float* sh_s, int* sh_c,
                                               float2* sh_res) {
    float sre = 0.f, sim = 0.f; int cre = 0, cim = 0;
    for (int i = threadIdx.x; i < npart; i += NTHR) {
        Part p = part[i];
        sre += p.sre; sim += p.sim; cre += p.cre; cim += p.cim;
    }
    #pragma unroll
    for (int o = 16; o > 0; o >>= 1) {
        sre += __shfl_down_sync(0xffffffffu, sre, o);
        sim += __shfl_down_sync(0xffffffffu, sim, o);
        cre += __shfl_down_sync(0xffffffffu, cre, o);
        cim += __shfl_down_sync(0xffffffffu, cim, o);
    }
    int lane = threadIdx.x & 31, wrp = threadIdx.x >> 5;
    if (lane == 0) {
        sh_s[wrp] = sre; sh_s[8 + wrp] = sim;
        sh_c[wrp] = cre; sh_c[8 + wrp] = cim;
    }
    __syncthreads();
    if (threadIdx.x == 0) {
        float a = 0.f, b = 0.f; int cc = 0, d = 0;
        #pragma unroll
        for (int i = 0; i < 8; i++) {
            a += sh_s[i]; b += sh_s[8 + i]; cc += sh_c[i]; d += sh_c[8 + i];
        }
        sh_res->x = fmaxf(a / fmaxf((float)cc, 1.0f), 1e-6f);
        sh_res->y = fmaxf(b / fmaxf((float)d, 1.0f), 1e-6f);
    }
    __syncthreads();
    return *sh_res;
}

// ---------------- Pass 1: stats of raw w -> g_part1 ----------------
__global__ void __launch_bounds__(NTHR, 6)
k_pass1(const float* __restrict__ re, const float* __restrict__ im, int n) {
    float s0re = 0.f, s0im = 0.f, s1re = 0.f, s1im = 0.f;
    int   c0re = 0, c0im = 0, c1re = 0, c1im = 0;
    int gtid = blockIdx.x * NTHR + threadIdx.x;
    int stride = gridDim.x * NTHR;
    int n4 = n >> 2;
    const float4* re4 = reinterpret_cast<const float4*>(re);
    const float4* im4 = reinterpret_cast<const float4*>(im);
    int i = gtid;
    for (; i + 3 * stride < n4; i += 4 * stride) {
        float4 a0 = __ldcs(&re4[i]);
        float4 a1 = __ldcs(&re4[i + stride]);
        float4 a2 = __ldcs(&re4[i + 2 * stride]);
        float4 a3 = __ldcs(&re4[i + 3 * stride]);
        float4 b0 = __ldcs(&im4[i]);
        float4 b1 = __ldcs(&im4[i + stride]);
        float4 b2 = __ldcs(&im4[i + 2 * stride]);
        float4 b3 = __ldcs(&im4[i + 3 * stride]);
        acc_stats(a0.x, b0.x, s0re, s0im, c0re, c0im);
        acc_stats(a0.y, b0.y, s1re, s1im, c1re, c1im);
        acc_stats(a0.z, b0.z, s0re, s0im, c0re, c0im);
        acc_stats(a0.w, b0.w, s1re, s1im, c1re, c1im);
        acc_stats(a1.x, b1.x, s0re, s0im, c0re, c0im);
        acc_stats(a1.y, b1.y, s1re, s1im, c1re, c1im);
        acc_stats(a1.z, b1.z, s0re, s0im, c0re, c0im);
        acc_stats(a1.w, b1.w, s1re, s1im, c1re, c1im);
        acc_stats(a2.x, b2.x, s0re, s0im, c0re, c0im);
        acc_stats(a2.y, b2.y, s1re, s1im, c1re, c1im);
        acc_stats(a2.z, b2.z, s0re, s0im, c0re, c0im);
        acc_stats(a2.w, b2.w, s1re, s1im, c1re, c1im);
        acc_stats(a3.x, b3.x, s0re, s0im, c0re, c0im);
        acc_stats(a3.y, b3.y, s1re, s1im, c1re, c1im);
        acc_stats(a3.z, b3.z, s0re, s0im, c0re, c0im);
        acc_stats(a3.w, b3.w, s1re, s1im, c1re, c1im);
    }
    for (; i < n4; i += stride) {
        float4 a0 = __ldcs(&re4[i]), b0 = __ldcs(&im4[i]);
        acc_stats(a0.x, b0.x, s0re, s0im, c0re, c0im);
        acc_stats(a0.y, b0.y, s1re, s1im, c1re, c1im);
        acc_stats(a0.z, b0.z, s0re, s0im, c0re, c0im);
        acc_stats(a0.w, b0.w, s1re, s1im, c1re, c1im);
    }
    for (int j = (n4 << 2) + gtid; j < n; j += stride)
        acc_stats(re[j], im[j], s0re, s0im, c0re, c0im);
    stats_reduce_store(g_part1, s0re + s1re, s0im + s1im,
                       c0re + c1re, c0im + c1im);
}

// ------- Pass 2: s1 = reduce(g_part1); stats of err1 -> g_part2 -------
__global__ void __launch_bounds__(NTHR)
k_pass2(const float* __restrict__ re, const float* __restrict__ im,
        const float* __restrict__ temp, int n, int npart1) {
    __shared__ float  sh_s[16];
    __shared__ int    sh_c[16];
    __shared__ float2 sh_res;
    float2 s1 = final_reduce(g_part1, npart1, sh_s, sh_c, &sh_res);
    Coef  c  = make_coef(temp);
    PCoef pc = make_pcoef(c, s1);

    float s0re = 0.f, s0im = 0.f, s1re_ = 0.f, s1im_ = 0.f;
    int   c0re = 0, c0im = 0, c1re = 0, c1im = 0;
    int gtid = blockIdx.x * NTHR + threadIdx.x;
    int stride = gridDim.x * NTHR;
    int n4 = n >> 2;
    const float4* re4 = reinterpret_cast<const float4*>(re);
    const float4* im4 = reinterpret_cast<const float4*>(im);

    auto body = [&](const float4& a, const float4& b) {
        u64 rxy = pk(a.x, a.y), ixy = pk(b.x, b.y);
        u64 rzw = pk(a.z, a.w), izw = pk(b.z, b.w);
        u64 q0r, q0i, q1r, q1i;
        quant_eval2p(rxy, ixy, pc, q0r, q0i);
        quant_eval2p(rzw, izw, pc, q1r, q1i);
        u64 e0r = fma2(q0r, pc.negone, rxy);   // err = w - q
        u64 e0i = fma2(q0i, pc.negone, ixy);
        u64 e1r = fma2(q1r, pc.negone, rzw);
        u64 e1i = fma2(q1i, pc.negone, izw);
        float x0, x1, y0, y1;
        upk(e0r, x0, x1); upk(e0i, y0, y1);
        acc_stats(x0, y0, s0re, s0im, c0re, c0im);
        acc_stats(x1, y1, s1re_, s1im_, c1re, c1im);
        upk(e1r, x0, x1); upk(e1i, y0, y1);
        acc_stats(x0, y0, s0re, s0im, c0re, c0im);
        acc_stats(x1, y1, s1re_, s1im_, c1re, c1im);
    };

    int i = gtid;
    if (i + stride < n4) {
        float4 a0 = __ldcs(&re4[i]),          b0 = __ldcs(&im4[i]);
        float4 a1 = __ldcs(&re4[i + stride]), b1 = __ldcs(&im4[i + stride]);
        for (; i + 3 * stride < n4; i += 2 * stride) {
            float4 a2 = __ldcs(&re4[i + 2 * stride]);
            float4 b2 = __ldcs(&im4[i + 2 * stride]);
            float4 a3 = __ldcs(&re4[i + 3 * stride]);
            float4 b3 = __ldcs(&im4[i + 3 * stride]);
            body(a0, b0);
            body(a1, b1);
            a0 = a2; b0 = b2; a1 = a3; b1 = b3;
        }
        body(a0, b0);
        body(a1, b1);
        i += 2 * stride;
    }
    for (; i < n4; i += stride) {
        float4 a = __ldcs(&re4[i]), b = __ldcs(&im4[i]);
        body(a, b);
    }
    for (int j = (n4 << 2) + gtid; j < n; j += stride) {
        float qr, qi;
        quant_eval(re[j], im[j], s1.x, s1.y, c, qr, qi);
        acc_stats(re[j] - qr, im[j] - qi, s0re, s0im, c0re, c0im);
    }
    stats_reduce_store(g_part2, s0re + s1re_, s0im + s1im_,
                       c0re + c1re, c0im + c1im);
}

// ------- Pass 3: s1,s2 reduces; out = q1 + q2 -------
__global__ void __launch_bounds__(NTHR)
k_pass3(const float* __restrict__ re, const float* __restrict__ im,
        const float* __restrict__ temp,
        float* __restrict__ out_re, float* __restrict__ out_im, int n,
        int npart1, int npart2) {
    __shared__ float  sh_s[16];
    __shared__ int    sh_c[16];
    __shared__ float2 sh_res1, sh_res2;
    float2 s1 = final_reduce(g_part1, npart1, sh_s, sh_c, &sh_res1);
    __syncthreads();
    float2 s2 = final_reduce(g_part2, npart2, sh_s, sh_c, &sh_res2);
    Coef  c   = make_coef(temp);
    PCoef pc1 = make_pcoef(c, s1);
    PCoef pc2 = make_pcoef(c, s2);

    int gtid = blockIdx.x * NTHR + threadIdx.x;
    int stride = gridDim.x * NTHR;
    int n4 = n >> 2;
    const float4* re4 = reinterpret_cast<const float4*>(re);
    const float4* im4 = reinterpret_cast<const float4*>(im);
    float4* or4 = reinterpret_cast<float4*>(out_re);
    float4* oi4 = reinterpret_cast<float4*>(out_im);

    auto half = [&](u64 r01, u64 i01, u64& outr, u64& outi) {
        u64 q1r, q1i, q2r, q2i;
        quant_eval2p(r01, i01, pc1, q1r, q1i);
        u64 er = fma2(q1r, pc1.negone, r01);   // err1 = w - q1
        u64 ei = fma2(q1i, pc1.negone, i01);
        quant_eval2p(er, ei, pc2, q2r, q2i);
        outr = add2(q1r, q2r);
        outi = add2(q1i, q2i);
    };

    auto body = [&](const float4& a, const float4& b, int idx) {
        u64 oxyr, oxyi, ozwr, ozwi;
        half(pk(a.x, a.y), pk(b.x, b.y), oxyr, oxyi);
        half(pk(a.z, a.w), pk(b.z, b.w), ozwr, ozwi);
        float4 qr4, qi4;
        upk(oxyr, qr4.x, qr4.y); upk(ozwr, qr4.z, qr4.w);
        upk(oxyi, qi4.x, qi4.y); upk(ozwi, qi4.z, qi4.w);
        __stcs(&or4[idx], qr4);
        __stcs(&oi4[idx], qi4);
    };

    int i = gtid;
    if (i + stride < n4) {
        float4 a0 = __ldcs(&re4[i]),          b0 = __ldcs(&im4[i]);
        float4 a1 = __ldcs(&re4[i + stride]), b1 = __ldcs(&im4[i + stride]);
        for (; i + 3 * stride < n4; i += 2 * stride) {
            float4 a2 = __ldcs(&re4[i + 2 * stride]);
            float4 b2 = __ldcs(&im4[i + 2 * stride]);
            float4 a3 = __ldcs(&re4[i + 3 * stride]);
            float4 b3 = __ldcs(&im4[i + 3 * stride]);
            body(a0, b0, i);
            body(a1, b1, i + stride);
            a0 = a2; b0 = b2; a1 = a3; b1 = b3;
        }
        body(a0, b0, i);
        body(a1, b1, i + stride);
        i += 2 * stride;
    }
    for (; i < n4; i += stride) {
        float4 a = __ldcs(&re4[i]), b = __ldcs(&im4[i]);
        body(a, b, i);
    }
    for (int j = (n4 << 2) + gtid; j < n; j += stride) {
        float q1r, q1i, q2r, q2i;
        quant_eval(re[j], im[j], s1.x, s1.y, c, q1r, q1i);
        quant_eval(re[j] - q1r, im[j] - q1i, s2.x, s2.y, c, q2r, q2i);
        out_re[j] = q1r + q2r;
        out_im[j] = q1i + q2i;
    }
}

static inline int clampi(int v, int lo, int hi) {
    return v < lo ? lo : (v > hi ? hi : v);
}

extern "C" void kernel_launch(void* const* d_in, const int* in_sizes, int n_in,
                              void* d_out, int out_size) {
    const float* w_re = (const float*)d_in[0];
    const float* w_im = (const float*)d_in[1];
    const float* temp = (const float*)d_in[2];
    int n = in_sizes[0];
    float* out_re = (float*)d_out;
    float* out_im = out_re + n;

    int dev = 0;
    cudaGetDevice(&dev);
    int sms = 148;
    cudaDeviceGetAttribute(&sms, cudaDevAttrMultiProcessorCount, dev);
    int b1 = 6, b2 = 4, b3 = 4;
    cudaOccupancyMaxActiveBlocksPerMultiprocessor(&b1, k_pass1, NTHR, 0);
    cudaOccupancyMaxActiveBlocksPerMultiprocessor(&b2, k_pass2, NTHR, 0);
    cudaOccupancyMaxActiveBlocksPerMultiprocessor(&b3, k_pass3, NTHR, 0);
    int g1 = clampi(b1 * sms, sms, NBLK_MAX);          // single wave
    int g2 = clampi(2 * b2 * sms, sms, NBLK_MAX);      // two waves
    int g3 = clampi(2 * b3 * sms, sms, NBLK_MAX);      // two waves

    k_pass1<<<g1, NTHR>>>(w_re, w_im, n);
    k_pass2<<<g2, NTHR>>>(w_re, w_im, temp, n, g1);
    k_pass3<<<g3, NTHR>>>(w_re, w_im, temp, out_re, out_im, n, g1, g2);
}